// round 14
// baseline (speedup 1.0000x reference)
#include <cuda_runtime.h>
#include <cuda_fp16.h>

#define IN_CH 65
#define HID   64
#define NPAIR 33   // ceil(65/2) packed k-pairs
#define MAX_NODES 100000
#define CAP      128   // bucket capacity per node (deg ~ Poisson(32))

typedef unsigned long long ull;

// ---------------------------------------------------------------------------
// Static scratch (no device-memory allocations allowed).
// g_cursor relies on zero-init for the first call; aggregate_kernel re-zeroes
// it on every execution (replay-safe invariant).
// ---------------------------------------------------------------------------
__device__ __align__(16) __half g_yh[(size_t)MAX_NODES * HID];  // y in fp16
__device__ int  g_cursor[MAX_NODES];                            // bucket fill counts
__device__ int2 g_entries[(size_t)MAX_NODES * CAP];             // (src, bits(w)) buckets

// ---------------------------------------------------------------------------
// Packed f32x2 helpers (Blackwell FFMA2 — only reachable via PTX)
// ---------------------------------------------------------------------------
__device__ __forceinline__ ull pack_f32x2(float lo, float hi) {
    ull r;
    asm("mov.b64 %0, {%1, %2};" : "=l"(r) : "f"(lo), "f"(hi));
    return r;
}
__device__ __forceinline__ void unpack_f32x2(ull v, float& lo, float& hi) {
    asm("mov.b64 {%0, %1}, %2;" : "=f"(lo), "=f"(hi) : "l"(v));
}
__device__ __forceinline__ void fma_f32x2(ull& d, ull a, ull b) {
    asm("fma.rn.f32x2 %0, %1, %2, %0;" : "+l"(d) : "l"(a), "l"(b));
}

// ---------------------------------------------------------------------------
// Kernel: per-node dual matvec (validated: 56.2us, 128 regs).
// 4 nodes/iter, double-buffered smem x, register prefetch; W_rel in regs,
// W_root in smem (conflict-free 8B/lane, reused across the 4 nodes).
//   g_yh[n] = half(W_rel @ x[n]);  out[n] = W_root @ x[n] + b_rel
// ---------------------------------------------------------------------------
__global__ __launch_bounds__(64, 8) void transform_kernel(
    const float* __restrict__ x,
    const float* __restrict__ W_rel,
    const float* __restrict__ b_rel,
    const float* __restrict__ W_root,
    float* __restrict__ out,
    int n_nodes)
{
    const int o = threadIdx.x;  // 0..63 output channel

    ull wrp[NPAIR];
    __shared__ ull wop_s[NPAIR][64];
#pragma unroll
    for (int p = 0; p < NPAIR; ++p) {
        const int k0 = 2 * p, k1 = 2 * p + 1;
        const float r0 = W_rel[o * IN_CH + k0];
        const float r1 = (k1 < IN_CH) ? W_rel[o * IN_CH + k1] : 0.0f;
        const float o0 = W_root[o * IN_CH + k0];
        const float o1 = (k1 < IN_CH) ? W_root[o * IN_CH + k1] : 0.0f;
        wrp[p] = pack_f32x2(r0, r1);
        wop_s[p][o] = pack_f32x2(o0, o1);
    }
    const float bias = b_rel[o];

    __shared__ __align__(16) float sx[2][4][68];
    if (o < 24) {
        const int b = o / 12, nd = (o % 12) / 3, k = 65 + (o % 3);
        sx[b][nd][k] = 0.0f;
    }

    const int total_elems = n_nodes * IN_CH;
    const int stride = gridDim.x * 4;

    int n0 = blockIdx.x * 4;

    {
        const int base = n0 * IN_CH;
#pragma unroll
        for (int j = 0; j < 5; ++j) {
            const int idx = o + j * 64;
            if (idx < 4 * IN_CH && base + idx < total_elems) {
                const int nd = idx / IN_CH;
                const int k  = idx - nd * IN_CH;
                sx[0][nd][k] = x[base + idx];
            }
        }
    }
    __syncthreads();   // covers wop_s + sx buffer 0

    for (int it = 0; n0 < n_nodes; n0 += stride, ++it) {
        const int buf = it & 1;

        const int nn = n0 + stride;
        float pf[5];
#pragma unroll
        for (int j = 0; j < 5; ++j) {
            const int idx = o + j * 64;
            const int gidx = nn * IN_CH + idx;
            pf[j] = (idx < 4 * IN_CH && nn < n_nodes && gidx < total_elems)
                        ? x[gidx] : 0.0f;
        }

        const ull* sp0 = reinterpret_cast<const ull*>(sx[buf][0]);
        const ull* sp1 = reinterpret_cast<const ull*>(sx[buf][1]);
        const ull* sp2 = reinterpret_cast<const ull*>(sx[buf][2]);
        const ull* sp3 = reinterpret_cast<const ull*>(sx[buf][3]);

        ull aY0 = 0, aY1 = 0, aY2 = 0, aY3 = 0;
        ull aO0 = 0, aO1 = 0, aO2 = 0, aO3 = 0;
#pragma unroll
        for (int p = 0; p < NPAIR; ++p) {
            const ull w_r = wrp[p];
            const ull w_o = wop_s[p][o];
            const ull x0 = sp0[p], x1 = sp1[p], x2 = sp2[p], x3 = sp3[p];
            fma_f32x2(aY0, w_r, x0); fma_f32x2(aO0, w_o, x0);
            fma_f32x2(aY1, w_r, x1); fma_f32x2(aO1, w_o, x1);
            fma_f32x2(aY2, w_r, x2); fma_f32x2(aO2, w_o, x2);
            fma_f32x2(aY3, w_r, x3); fma_f32x2(aO3, w_o, x3);
        }

        float lo, hi;
#define STORE_NODE(idx, AY, AO)                                              \
        if (n0 + (idx) < n_nodes) {                                         \
            unpack_f32x2(AY, lo, hi);                                       \
            g_yh[(size_t)(n0 + (idx)) * HID + o] = __float2half(lo + hi);   \
            unpack_f32x2(AO, lo, hi);                                       \
            out[(size_t)(n0 + (idx)) * HID + o] = lo + hi + bias;           \
        }
        STORE_NODE(0, aY0, aO0)
        STORE_NODE(1, aY1, aO1)
        STORE_NODE(2, aY2, aO2)
        STORE_NODE(3, aY3, aO3)
#undef STORE_NODE

#pragma unroll
        for (int j = 0; j < 5; ++j) {
            const int idx = o + j * 64;
            if (idx < 4 * IN_CH) {
                const int nd = idx / IN_CH;
                const int k  = idx - nd * IN_CH;
                sx[buf ^ 1][nd][k] = pf[j];
            }
        }
        __syncthreads();
    }
}

// ---------------------------------------------------------------------------
// Kernel: direct bucket fill. One thread per edge: atomically claim a slot in
// dst's fixed-capacity bucket, store (src, bits(w)).
// ---------------------------------------------------------------------------
__global__ void fill_direct_kernel(const int* __restrict__ ei,
                                   const float* __restrict__ ew, int E)
{
    const int e = blockIdx.x * blockDim.x + threadIdx.x;
    if (e >= E) return;
    const int src = __ldg(ei + e);
    const int dst = __ldg(ei + E + e);
    const float w = __ldg(ew + e);
    const int pos = atomicAdd(&g_cursor[dst], 1);
    if (pos < CAP)
        g_entries[(size_t)dst * CAP + pos] = make_int2(src, __float_as_int(w));
}

// ---------------------------------------------------------------------------
// Kernel: atomic-free aggregation over fp16 y, SOFTWARE-PIPELINED entry
// stream. 8-lane group owns one node; each lane covers 8 channels. The next
// entry pair is prefetched at the top of the body, overlapping its L2 latency
// with the current pair's y-gathers + FMAs (collapses the serial
// entry->y->fma chain from ~2 L2 latencies/iter to ~1). Tail is handled with
// group-uniform w=0 / src=0 masking (harmless row-0 gather). Lane 0 re-zeroes
// the node's cursor after reading (replay invariant).
// ---------------------------------------------------------------------------
__global__ __launch_bounds__(256) void aggregate_kernel(
    float* __restrict__ out, int n_nodes)
{
    const int tid = threadIdx.x;
    const int sub = tid & 7;                        // channel octet 0..7
    const int grp = tid >> 3;                       // group slot 0..31
    const int n   = blockIdx.x * 32 + grp;
    if (n >= n_nodes) return;

    int cnt = g_cursor[n];
    if (sub == 0) g_cursor[n] = 0;                  // reset for next call
    if (cnt > CAP) cnt = CAP;

    const int2* __restrict__ bucket = g_entries + (size_t)n * CAP;

    float acc[8];
#pragma unroll
    for (int c = 0; c < 8; ++c) acc[c] = 0.0f;

    const int2 znt = make_int2(0, 0);   // masked entry: src=0, w=+0.0f

    // Prologue: load the first entry pair (masked beyond cnt).
    int2 c0 = (0 < cnt) ? __ldg(bucket + 0) : znt;
    int2 c1 = (1 < cnt) ? __ldg(bucket + 1) : znt;

    for (int j = 0; j < cnt; j += 2) {
        // Prefetch the NEXT pair first — overlaps its latency with the
        // current pair's gathers + FMAs below.
        const int2 n0 = (j + 2 < cnt) ? __ldg(bucket + j + 2) : znt;
        const int2 n1 = (j + 3 < cnt) ? __ldg(bucket + j + 3) : znt;

        const float w0 = __int_as_float(c0.y);
        const float w1 = __int_as_float(c1.y);
        const uint4 v0 = *reinterpret_cast<const uint4*>(
            g_yh + (size_t)c0.x * HID + sub * 8);
        const uint4 v1 = *reinterpret_cast<const uint4*>(
            g_yh + (size_t)c1.x * HID + sub * 8);
        const unsigned* p0 = &v0.x;
        const unsigned* p1 = &v1.x;
#pragma unroll
        for (int q = 0; q < 4; ++q) {
            const float2 f0 = __half22float2(
                *reinterpret_cast<const __half2*>(&p0[q]));
            const float2 f1 = __half22float2(
                *reinterpret_cast<const __half2*>(&p1[q]));
            acc[2*q]   = fmaf(w0, f0.x, acc[2*q]);
            acc[2*q+1] = fmaf(w0, f0.y, acc[2*q+1]);
            acc[2*q]   = fmaf(w1, f1.x, acc[2*q]);
            acc[2*q+1] = fmaf(w1, f1.y, acc[2*q+1]);
        }

        c0 = n0;
        c1 = n1;
    }

    float4* p = reinterpret_cast<float4*>(out + (size_t)n * HID + sub * 8);
    float4 a = p[0], b = p[1];
    a.x += acc[0]; a.y += acc[1]; a.z += acc[2]; a.w += acc[3];
    b.x += acc[4]; b.y += acc[5]; b.z += acc[6]; b.w += acc[7];
    p[0] = a; p[1] = b;
}

// ---------------------------------------------------------------------------
// One-time side-stream/event setup (host objects only — no device memory).
// ---------------------------------------------------------------------------
struct ForkCtx {
    cudaStream_t s2;
    cudaEvent_t  ev_fork, ev_join;
    ForkCtx() {
        cudaStreamCreateWithFlags(&s2, cudaStreamNonBlocking);
        cudaEventCreateWithFlags(&ev_fork, cudaEventDisableTiming);
        cudaEventCreateWithFlags(&ev_join, cudaEventDisableTiming);
    }
};
static ForkCtx& fork_ctx() { static ForkCtx c; return c; }

// ---------------------------------------------------------------------------
extern "C" void kernel_launch(void* const* d_in, const int* in_sizes, int n_in,
                              void* d_out, int out_size)
{
    const float* x      = (const float*)d_in[0];
    const int*   ei     = (const int*)d_in[1];
    const float* ew     = (const float*)d_in[2];
    const float* W_rel  = (const float*)d_in[3];
    const float* b_rel  = (const float*)d_in[4];
    const float* W_root = (const float*)d_in[5];
    float*       out    = (float*)d_out;

    const int n_nodes = in_sizes[0] / IN_CH;
    const int E       = in_sizes[1] / 2;   // edge_index is [2, E] int32

    ForkCtx& fc = fork_ctx();

    // Fork: transform (writes out + g_yh) on side stream.
    cudaEventRecord(fc.ev_fork, 0);
    cudaStreamWaitEvent(fc.s2, fc.ev_fork, 0);
    transform_kernel<<<2048, 64, 0, fc.s2>>>(x, W_rel, b_rel, W_root,
                                             out, n_nodes);
    cudaEventRecord(fc.ev_join, fc.s2);

    // Main stream: single-kernel bucket build (parallel to transform).
    fill_direct_kernel<<<(E + 255) / 256, 256>>>(ei, ew, E);

    // Join, then aggregate: out[n] += sum_{e: dst=n} w_e * y[src_e]
    cudaStreamWaitEvent(0, fc.ev_join, 0);
    aggregate_kernel<<<(n_nodes + 31) / 32, 256>>>(out, n_nodes);
}

// round 15
// speedup vs baseline: 1.0239x; 1.0239x over previous
#include <cuda_runtime.h>
#include <cuda_fp16.h>

#define IN_CH 65
#define HID   64
#define NPAIR 33   // ceil(65/2) packed k-pairs
#define NODES_PER_IT 8
#define MAX_NODES 100000
#define CAP      128   // bucket capacity per node (deg ~ Poisson(32))

typedef unsigned long long ull;

// ---------------------------------------------------------------------------
// Static scratch (no device-memory allocations allowed).
// g_cursor relies on zero-init for the first call; aggregate_kernel re-zeroes
// it on every execution (replay-safe invariant).
// ---------------------------------------------------------------------------
__device__ __align__(16) __half g_yh[(size_t)MAX_NODES * HID];  // y in fp16
__device__ int  g_cursor[MAX_NODES];                            // bucket fill counts
__device__ int2 g_entries[(size_t)MAX_NODES * CAP];             // (src, bits(w)) buckets

// ---------------------------------------------------------------------------
// Packed f32x2 helpers (Blackwell FFMA2 — only reachable via PTX)
// ---------------------------------------------------------------------------
__device__ __forceinline__ ull pack_f32x2(float lo, float hi) {
    ull r;
    asm("mov.b64 %0, {%1, %2};" : "=l"(r) : "f"(lo), "f"(hi));
    return r;
}
__device__ __forceinline__ void unpack_f32x2(ull v, float& lo, float& hi) {
    asm("mov.b64 {%0, %1}, %2;" : "=f"(lo), "=f"(hi) : "l"(v));
}
__device__ __forceinline__ void fma_f32x2(ull& d, ull a, ull b) {
    asm("fma.rn.f32x2 %0, %1, %2, %0;" : "+l"(d) : "l"(a), "l"(b));
}

// ---------------------------------------------------------------------------
// Kernel: per-node dual matvec. Crossbar-optimized: 8 nodes/iteration
// (W_root smem reads amortized 8x) and 16B (ulonglong2) broadcast LDS for x
// (broadcast costs ~1 crossbar cycle regardless of width). W_rel in regs,
// W_root in smem; double-buffered smem x with register prefetch.
//   g_yh[n] = half(W_rel @ x[n]);  out[n] = W_root @ x[n] + b_rel
// ---------------------------------------------------------------------------
__global__ __launch_bounds__(64, 6) void transform_kernel(
    const float* __restrict__ x,
    const float* __restrict__ W_rel,
    const float* __restrict__ b_rel,
    const float* __restrict__ W_root,
    float* __restrict__ out,
    int n_nodes)
{
    const int o = threadIdx.x;  // 0..63 output channel

    ull wrp[NPAIR];
    __shared__ ull wop_s[NPAIR][64];
#pragma unroll
    for (int p = 0; p < NPAIR; ++p) {
        const int k0 = 2 * p, k1 = 2 * p + 1;
        const float r0 = W_rel[o * IN_CH + k0];
        const float r1 = (k1 < IN_CH) ? W_rel[o * IN_CH + k1] : 0.0f;
        const float o0 = W_root[o * IN_CH + k0];
        const float o1 = (k1 < IN_CH) ? W_root[o * IN_CH + k1] : 0.0f;
        wrp[p] = pack_f32x2(r0, r1);
        wop_s[p][o] = pack_f32x2(o0, o1);
    }
    const float bias = b_rel[o];

    // Double-buffered x rows: 2 x 8 nodes x 68 floats. Row = 272B = 17*16B,
    // so every row (and every 4-float group) stays 16B-aligned.
    __shared__ __align__(16) float sx[2][NODES_PER_IT][68];
    // Zero pad slots k=65..67 (2*8*3 = 48 values).
    if (o < 48) {
        const int b = o / 24, nd = (o % 24) / 3, k = 65 + (o % 3);
        sx[b][nd][k] = 0.0f;
    }

    const int total_elems = n_nodes * IN_CH;
    const int stride = gridDim.x * NODES_PER_IT;

    int n0 = blockIdx.x * NODES_PER_IT;

    // Stage iteration 0 into buffer 0 (8*65 = 520 elements, 64 threads).
    {
        const int base = n0 * IN_CH;
#pragma unroll
        for (int j = 0; j < 9; ++j) {
            const int idx = o + j * 64;
            if (idx < NODES_PER_IT * IN_CH && base + idx < total_elems) {
                const int nd = idx / IN_CH;
                const int k  = idx - nd * IN_CH;
                sx[0][nd][k] = x[base + idx];
            }
        }
    }
    __syncthreads();   // covers wop_s + sx buffer 0

    for (int it = 0; n0 < n_nodes; n0 += stride, ++it) {
        const int buf = it & 1;

        // Prefetch next iteration's rows into registers.
        const int nn = n0 + stride;
        float pf[9];
#pragma unroll
        for (int j = 0; j < 9; ++j) {
            const int idx = o + j * 64;
            const int gidx = nn * IN_CH + idx;
            pf[j] = (idx < NODES_PER_IT * IN_CH && nn < n_nodes &&
                     gidx < total_elems) ? x[gidx] : 0.0f;
        }

        // 8 nodes x 2 matrices = 16 independent packed chains.
        ull aY[NODES_PER_IT], aO[NODES_PER_IT];
#pragma unroll
        for (int nd = 0; nd < NODES_PER_IT; ++nd) { aY[nd] = 0; aO[nd] = 0; }

        // Pairs 0..31 via 16B broadcast loads (2 packed pairs per LDS.128).
#pragma unroll
        for (int pp = 0; pp < 16; ++pp) {
            const ull wr0 = wrp[2 * pp],     wr1 = wrp[2 * pp + 1];
            const ull wo0 = wop_s[2 * pp][o], wo1 = wop_s[2 * pp + 1][o];
#pragma unroll
            for (int nd = 0; nd < NODES_PER_IT; ++nd) {
                const ulonglong2 xv = *reinterpret_cast<const ulonglong2*>(
                    &sx[buf][nd][4 * pp]);
                fma_f32x2(aY[nd], wr0, xv.x);
                fma_f32x2(aO[nd], wo0, xv.x);
                fma_f32x2(aY[nd], wr1, xv.y);
                fma_f32x2(aO[nd], wo1, xv.y);
            }
        }
        // Tail pair p=32 (floats 64..65; 65 is x data, 66-67 pad are unused).
        {
            const ull wr = wrp[32];
            const ull wo = wop_s[32][o];
#pragma unroll
            for (int nd = 0; nd < NODES_PER_IT; ++nd) {
                const ull xv = *reinterpret_cast<const ull*>(&sx[buf][nd][64]);
                fma_f32x2(aY[nd], wr, xv);
                fma_f32x2(aO[nd], wo, xv);
            }
        }

        // Store results.
#pragma unroll
        for (int nd = 0; nd < NODES_PER_IT; ++nd) {
            if (n0 + nd < n_nodes) {
                float lo, hi;
                unpack_f32x2(aY[nd], lo, hi);
                g_yh[(size_t)(n0 + nd) * HID + o] = __float2half(lo + hi);
                unpack_f32x2(aO[nd], lo, hi);
                out[(size_t)(n0 + nd) * HID + o] = lo + hi + bias;
            }
        }

        // Commit prefetched rows to the other buffer.
#pragma unroll
        for (int j = 0; j < 9; ++j) {
            const int idx = o + j * 64;
            if (idx < NODES_PER_IT * IN_CH) {
                const int nd = idx / IN_CH;
                const int k  = idx - nd * IN_CH;
                sx[buf ^ 1][nd][k] = pf[j];
            }
        }
        __syncthreads();
    }
}

// ---------------------------------------------------------------------------
// Kernel: direct bucket fill. One thread per edge: atomically claim a slot in
// dst's fixed-capacity bucket, store (src, bits(w)).
// ---------------------------------------------------------------------------
__global__ void fill_direct_kernel(const int* __restrict__ ei,
                                   const float* __restrict__ ew, int E)
{
    const int e = blockIdx.x * blockDim.x + threadIdx.x;
    if (e >= E) return;
    const int src = __ldg(ei + e);
    const int dst = __ldg(ei + E + e);
    const float w = __ldg(ew + e);
    const int pos = atomicAdd(&g_cursor[dst], 1);
    if (pos < CAP)
        g_entries[(size_t)dst * CAP + pos] = make_int2(src, __float_as_int(w));
}

// ---------------------------------------------------------------------------
// Kernel: atomic-free aggregation over fp16 y (validated 144.5-baseline
// version — do not restructure). 8-lane group owns one node; each lane covers
// 8 channels, unroll-2 entry loop, fp32 accum, one plain RMW into out.
// Lane 0 re-zeroes the node's cursor after reading (replay invariant).
// ---------------------------------------------------------------------------
__global__ __launch_bounds__(256) void aggregate_kernel(
    float* __restrict__ out, int n_nodes)
{
    const int tid = threadIdx.x;
    const int sub = tid & 7;                        // channel octet 0..7
    const int grp = tid >> 3;                       // group slot 0..31
    const int n   = blockIdx.x * 32 + grp;
    if (n >= n_nodes) return;

    int cnt = g_cursor[n];
    if (sub == 0) g_cursor[n] = 0;                  // reset for next call
    if (cnt > CAP) cnt = CAP;

    const int2* __restrict__ bucket = g_entries + (size_t)n * CAP;

    float acc[8];
#pragma unroll
    for (int c = 0; c < 8; ++c) acc[c] = 0.0f;

    int j = 0;
    for (; j + 1 < cnt; j += 2) {
        const int2 e0 = __ldg(bucket + j);
        const int2 e1 = __ldg(bucket + j + 1);
        const float w0 = __int_as_float(e0.y);
        const float w1 = __int_as_float(e1.y);
        const uint4 v0 = *reinterpret_cast<const uint4*>(
            g_yh + (size_t)e0.x * HID + sub * 8);
        const uint4 v1 = *reinterpret_cast<const uint4*>(
            g_yh + (size_t)e1.x * HID + sub * 8);
        const unsigned* p0 = &v0.x;
        const unsigned* p1 = &v1.x;
#pragma unroll
        for (int q = 0; q < 4; ++q) {
            const float2 f0 = __half22float2(
                *reinterpret_cast<const __half2*>(&p0[q]));
            const float2 f1 = __half22float2(
                *reinterpret_cast<const __half2*>(&p1[q]));
            acc[2*q]   = fmaf(w0, f0.x, acc[2*q]);
            acc[2*q+1] = fmaf(w0, f0.y, acc[2*q+1]);
            acc[2*q]   = fmaf(w1, f1.x, acc[2*q]);
            acc[2*q+1] = fmaf(w1, f1.y, acc[2*q+1]);
        }
    }
    if (j < cnt) {
        const int2 e0 = __ldg(bucket + j);
        const float w0 = __int_as_float(e0.y);
        const uint4 v0 = *reinterpret_cast<const uint4*>(
            g_yh + (size_t)e0.x * HID + sub * 8);
        const unsigned* p0 = &v0.x;
#pragma unroll
        for (int q = 0; q < 4; ++q) {
            const float2 f0 = __half22float2(
                *reinterpret_cast<const __half2*>(&p0[q]));
            acc[2*q]   = fmaf(w0, f0.x, acc[2*q]);
            acc[2*q+1] = fmaf(w0, f0.y, acc[2*q+1]);
        }
    }

    float4* p = reinterpret_cast<float4*>(out + (size_t)n * HID + sub * 8);
    float4 a = p[0], b = p[1];
    a.x += acc[0]; a.y += acc[1]; a.z += acc[2]; a.w += acc[3];
    b.x += acc[4]; b.y += acc[5]; b.z += acc[6]; b.w += acc[7];
    p[0] = a; p[1] = b;
}

// ---------------------------------------------------------------------------
// One-time side-stream/event setup (host objects only — no device memory).
// ---------------------------------------------------------------------------
struct ForkCtx {
    cudaStream_t s2;
    cudaEvent_t  ev_fork, ev_join;
    ForkCtx() {
        cudaStreamCreateWithFlags(&s2, cudaStreamNonBlocking);
        cudaEventCreateWithFlags(&ev_fork, cudaEventDisableTiming);
        cudaEventCreateWithFlags(&ev_join, cudaEventDisableTiming);
    }
};
static ForkCtx& fork_ctx() { static ForkCtx c; return c; }

// ---------------------------------------------------------------------------
extern "C" void kernel_launch(void* const* d_in, const int* in_sizes, int n_in,
                              void* d_out, int out_size)
{
    const float* x      = (const float*)d_in[0];
    const int*   ei     = (const int*)d_in[1];
    const float* ew     = (const float*)d_in[2];
    const float* W_rel  = (const float*)d_in[3];
    const float* b_rel  = (const float*)d_in[4];
    const float* W_root = (const float*)d_in[5];
    float*       out    = (float*)d_out;

    const int n_nodes = in_sizes[0] / IN_CH;
    const int E       = in_sizes[1] / 2;   // edge_index is [2, E] int32

    ForkCtx& fc = fork_ctx();

    // Fork: transform (writes out + g_yh) on side stream.
    cudaEventRecord(fc.ev_fork, 0);
    cudaStreamWaitEvent(fc.s2, fc.ev_fork, 0);
    transform_kernel<<<2048, 64, 0, fc.s2>>>(x, W_rel, b_rel, W_root,
                                             out, n_nodes);
    cudaEventRecord(fc.ev_join, fc.s2);

    // Main stream: single-kernel bucket build (parallel to transform).
    fill_direct_kernel<<<(E + 255) / 256, 256>>>(ei, ew, E);

    // Join, then aggregate: out[n] += sum_{e: dst=n} w_e * y[src_e]
    cudaStreamWaitEvent(0, fc.ev_join, 0);
    aggregate_kernel<<<(n_nodes + 31) / 32, 256>>>(out, n_nodes);
}